// round 2
// baseline (speedup 1.0000x reference)
#include <cuda_runtime.h>
#include <cuda_bf16.h>
#include <cstdint>

// Problem constants
#define TT   1024
#define BB   32
#define NH   8
#define DD   32
#define YD   97
#define INDIM 256          // NH*DD
#define ROWSTRIDE 8192     // BB*INDIM

typedef unsigned long long u64;

// -------- scratch (device globals; no allocation allowed) ----------
__device__ float g_x  [(size_t)TT * BB * INDIM];   // softmax(h), 33.5 MB
__device__ float g_fwm[(size_t)TT * BB * INDIM];   // FWM output pre-GEMM, 33.5 MB

// -------- packed f32x2 helpers ----------
__device__ __forceinline__ u64 ffma2(u64 a, u64 b, u64 c) {
    u64 d;
    asm("fma.rn.f32x2 %0, %1, %2, %3;" : "=l"(d) : "l"(a), "l"(b), "l"(c));
    return d;
}
__device__ __forceinline__ u64 pack2(float a, float b) {
    u64 r;
    asm("mov.b64 %0, {%1, %2};" : "=l"(r) : "f"(a), "f"(b));
    return r;
}
__device__ __forceinline__ u64 bcast2(float a) {
    u64 r;
    asm("mov.b64 %0, {%1, %1};" : "=l"(r) : "f"(a));
    return r;
}
__device__ __forceinline__ float hsum2(u64 v) {
    float a, b;
    asm("mov.b64 {%0, %1}, %2;" : "=f"(a), "=f"(b) : "l"(v));
    return a + b;
}
__device__ __forceinline__ u64 lds2(const float* p) {
    return *(const u64*)p;   // LDS.64, requires 8B alignment
}

// -------- warp reductions ----------
__device__ __forceinline__ float wmax(float v) {
#pragma unroll
    for (int o = 16; o; o >>= 1) v = fmaxf(v, __shfl_xor_sync(0xffffffffu, v, o));
    return v;
}
__device__ __forceinline__ float wsum(float v) {
#pragma unroll
    for (int o = 16; o; o >>= 1) v += __shfl_xor_sync(0xffffffffu, v, o);
    return v;
}
__device__ __forceinline__ float sigmoidf_(float x) {
    return 1.0f / (1.0f + __expf(-x));
}

// ======================================================================
// Kernel 0: x = softmax(h) over last dim D, rows = T*B*H
// ======================================================================
__global__ __launch_bounds__(256)
void softmax_x_kernel(const float* __restrict__ h) {
    int row  = blockIdx.x * 8 + (threadIdx.x >> 5);
    int lane = threadIdx.x & 31;
    float v = h[(size_t)row * DD + lane];
    float m = wmax(v);
    float p = __expf(v - m);
    float s = wsum(p);
    g_x[(size_t)row * DD + lane] = p / s;
}

// ======================================================================
// Kernel 1: SRWM + fast-weight-memory recurrence. One CTA per (b,h).
// 7 warps: columns of {Wy(97), wb(4), Wq(32), Wk(32), F(32)} register-resident.
// ======================================================================
__global__ __launch_bounds__(224, 2)
void srwm_kernel(const float* __restrict__ W_y, const float* __restrict__ W_q,
                 const float* __restrict__ W_k, const float* __restrict__ w_b,
                 const float* __restrict__ sW_y, const float* __restrict__ sW_q,
                 const float* __restrict__ sW_k, const float* __restrict__ sw_b,
                 const float* __restrict__ F0) {
    __shared__ __align__(16) float xs[2][DD];
    __shared__ __align__(16) float q_s[DD], k_s[DD], fq_s[DD], fk_s[DD], fv_s[DD];
    __shared__ __align__(16) float beta_s[4];
    __shared__ float fb_s;

    const int bh   = blockIdx.x;           // b*NH + h
    const int hh   = bh & (NH - 1);
    const int tid  = threadIdx.x;
    const int warp = tid >> 5;
    const int lane = tid & 31;

    // ---- role / column assignment ----
    // role 0: Wy col e (0..96)   -> beta[0]
    // role 1: wb col e (0..3)    -> beta[3]
    // role 2: Wq col e (0..31)   -> beta[1]
    // role 3: Wk col e (0..31)   -> beta[2]
    // role 4: F  col e (0..31)   (warp 6; also x staging + out STG)
    // role 5: idle (warp 3 lanes 5..31)
    int role = 5, e = 0;
    if (warp < 3)            { role = 0; e = warp * 32 + lane; }
    else if (warp == 3) {
        if (lane == 0)       { role = 0; e = 96; }
        else if (lane <= 4)  { role = 1; e = lane - 1; }
    }
    else if (warp == 4)      { role = 2; e = lane; }
    else if (warp == 5)      { role = 3; e = lane; }
    else                     { role = 4; e = lane; }

    const int bidx = (role == 0) ? 0 : (role == 2) ? 1 : (role == 3) ? 2 : 3;

    // ---- initial column load (state + broadcast weight) ----
    const float* sp = nullptr;
    const float* wp = nullptr;
    int stride = 0;
    switch (role) {
        case 0: sp = sW_y + (size_t)bh * DD * YD + e; wp = W_y + (size_t)hh * DD * YD + e; stride = YD; break;
        case 1: sp = sw_b + (size_t)bh * DD * 4  + e; wp = w_b + (size_t)hh * DD * 4  + e; stride = 4;  break;
        case 2: sp = sW_q + (size_t)bh * DD * DD + e; wp = W_q + (size_t)hh * DD * DD + e; stride = DD; break;
        case 3: sp = sW_k + (size_t)bh * DD * DD + e; wp = W_k + (size_t)hh * DD * DD + e; stride = DD; break;
        case 4: sp = F0   + (size_t)bh * DD * DD + e;                                       stride = DD; break;
        default: break;
    }
    u64 c[16];
    if (role <= 4) {
#pragma unroll
        for (int i = 0; i < 16; i++) {
            float v0 = sp[(2 * i)     * stride];
            float v1 = sp[(2 * i + 1) * stride];
            if (wp) { v0 += wp[(2 * i) * stride]; v1 += wp[(2 * i + 1) * stride]; }
            c[i] = pack2(v0, v1);
        }
    } else {
#pragma unroll
        for (int i = 0; i < 16; i++) c[i] = 0ull;
    }

    // ---- prologue: warp 6 stages x_0 into smem, prefetches x_1 ----
    float xreg = 0.0f;
    if (role == 4) {
        xs[0][lane] = g_x[(size_t)bh * DD + lane];
        xreg        = g_x[(size_t)ROWSTRIDE + bh * DD + lane];
    }
    __syncthreads();

    // ================= time loop =================
    for (int t = 0; t < TT; t++) {
        // ---------- phase 2: matvecs with OLD matrices ----------
        if (role <= 3) {
            const float* xp = xs[t & 1];
            u64 a0 = 0ull, a1 = 0ull;
#pragma unroll
            for (int i = 0; i < 8; i++) {
                a0 = ffma2(lds2(xp + 4 * i),     c[2 * i],     a0);
                a1 = ffma2(lds2(xp + 4 * i + 2), c[2 * i + 1], a1);
            }
            float yv = hsum2(a0) + hsum2(a1);

            if (warp == 0) {                       // fq = softmax(y[0:32])
                float m = wmax(yv); float p = __expf(yv - m); float s = wsum(p);
                fq_s[lane] = p / s;
            } else if (warp == 1) {                // fk = softmax(y[32:64])
                float m = wmax(yv); float p = __expf(yv - m); float s = wsum(p);
                fk_s[lane] = p / s;
            } else if (warp == 2) {                // fv = y[64:96]
                fv_s[lane] = yv;
            } else if (warp == 3) {                // fb / beta (no shuffles here)
                if (role == 0)      fb_s        = sigmoidf_(yv);   // y[96]
                else                beta_s[e]   = sigmoidf_(yv);
            } else if (warp == 4) {                // q = softmax(x Wq)
                float m = wmax(yv); float p = __expf(yv - m); float s = wsum(p);
                q_s[lane] = p / s;
            } else {                               // warp 5: k = softmax(x Wk)
                float m = wmax(yv); float p = __expf(yv - m); float s = wsum(p);
                k_s[lane] = p / s;
            }
        } else if (role == 4) {
            // warp 6: stage x_{t+1}, prefetch x_{t+2}
            if (t + 1 < TT) {
                xs[(t + 1) & 1][lane] = xreg;
                xreg = (t + 2 < TT) ? g_x[(size_t)(t + 2) * ROWSTRIDE + bh * DD + lane] : 0.0f;
            }
        }
        __syncthreads();   // q,k,beta,fq,fk,fv,fb and x_{t+1} ready

        // ---------- phase 3: updates ----------
        if (role <= 3) {
            // SRWM update:  col[d] += beta_i * k[d] * (vq_e - vk_e)
            float bi = beta_s[bidx];
            u64 vq0 = 0ull, vq1 = 0ull, vk0 = 0ull, vk1 = 0ull;
            u64 kc[16];
#pragma unroll
            for (int i = 0; i < 16; i += 2) {
                u64 q2 = lds2(q_s + 2 * i);
                u64 k2 = lds2(k_s + 2 * i);
                kc[i] = k2;
                vq0 = ffma2(q2, c[i], vq0);
                vk0 = ffma2(k2, c[i], vk0);
                u64 q3 = lds2(q_s + 2 * i + 2);
                u64 k3 = lds2(k_s + 2 * i + 2);
                kc[i + 1] = k3;
                vq1 = ffma2(q3, c[i + 1], vq1);
                vk1 = ffma2(k3, c[i + 1], vk1);
            }
            float vq = hsum2(vq0) + hsum2(vq1);
            float vk = hsum2(vk0) + hsum2(vk1);
            float delta = bi * (vq - vk);
            u64 d2 = bcast2(delta);
#pragma unroll
            for (int i = 0; i < 16; i++) c[i] = ffma2(kc[i], d2, c[i]);
        } else if (role == 4) {
            // FWM:  vold = fk.F ; F += fb*outer(fk, fv - vold) ; out = fq.F_new
            //       out_e = fq.F_old + fb*(fv_e - vold_e)*(fq.fk)
            u64 vo = 0ull, oq = 0ull, ss = 0ull;
            u64 fkc[16];
#pragma unroll
            for (int i = 0; i < 16; i++) {
                u64 fq2 = lds2(fq_s + 2 * i);
                u64 fk2 = lds2(fk_s + 2 * i);
                fkc[i] = fk2;
                vo = ffma2(fk2, c[i], vo);
                oq = ffma2(fq2, c[i], oq);
                ss = ffma2(fq2, fk2, ss);
            }
            float vold = hsum2(vo);
            float outq = hsum2(oq);
            float sqk  = hsum2(ss);
            float delta = fb_s * (fv_s[lane] - vold);
            u64 d2 = bcast2(delta);
#pragma unroll
            for (int i = 0; i < 16; i++) c[i] = ffma2(fkc[i], d2, c[i]);
            g_fwm[(size_t)t * ROWSTRIDE + bh * DD + lane] = outq + delta * sqk;
        }
        __syncthreads();   // protect q/k/... before next phase-2 overwrite
    }
}

// ======================================================================
// Kernel 2: out = h + g_fwm @ W_out^T    (M=32768, N=256, K=256)
// BM=128, BN=64, BK=16, 256 threads, thread tile 8x4 (f32x2 packed)
// ======================================================================
#define GBM 128
#define GBN 64
#define GBK 16

__global__ __launch_bounds__(256)
void out_gemm_kernel(const float* __restrict__ W,   // W_out [n][k], 256x256
                     const float* __restrict__ h,
                     float* __restrict__ out) {
    __shared__ float As[GBK][GBM];
    __shared__ float Bs[GBK][GBN];

    const int tid = threadIdx.x;
    const int m0  = blockIdx.x * GBM;
    const int n0  = blockIdx.y * GBN;
    const int ty  = tid >> 4;    // 0..15 -> m sub-tile
    const int tx  = tid & 15;    // 0..15 -> n sub-tile

    u64 acc[8][2];
#pragma unroll
    for (int i = 0; i < 8; i++) { acc[i][0] = 0ull; acc[i][1] = 0ull; }

    for (int kt = 0; kt < INDIM; kt += GBK) {
        // load A tile (g_fwm) 128x16 : 2 float4 per thread
#pragma unroll
        for (int r = 0; r < 2; r++) {
            int id  = tid + r * 256;
            int row = id >> 2;
            int kv  = (id & 3) * 4;
            float4 v = *(const float4*)(g_fwm + (size_t)(m0 + row) * INDIM + kt + kv);
            As[kv + 0][row] = v.x; As[kv + 1][row] = v.y;
            As[kv + 2][row] = v.z; As[kv + 3][row] = v.w;
        }
        // load B tile (W_out) 64x16 : 1 float4 per thread
        {
            int row = tid >> 2;
            int kv  = (tid & 3) * 4;
            float4 v = *(const float4*)(W + (size_t)(n0 + row) * INDIM + kt + kv);
            Bs[kv + 0][row] = v.x; Bs[kv + 1][row] = v.y;
            Bs[kv + 2][row] = v.z; Bs[kv + 3][row] = v.w;
        }
        __syncthreads();

#pragma unroll
        for (int k = 0; k < GBK; k++) {
            float4 a0 = *(const float4*)&As[k][ty * 8];
            float4 a1 = *(const float4*)&As[k][ty * 8 + 4];
            u64 b0 = lds2(&Bs[k][tx * 4]);
            u64 b1 = lds2(&Bs[k][tx * 4 + 2]);
            u64 p;
            p = bcast2(a0.x); acc[0][0] = ffma2(p, b0, acc[0][0]); acc[0][1] = ffma2(p, b1, acc[0][1]);
            p = bcast2(a0.y); acc[1][0] = ffma2(p, b0, acc[1][0]); acc[1][1] = ffma2(p, b1, acc[1][1]);
            p = bcast2(a0.z); acc[2][0] = ffma2(p, b0, acc[2][0]); acc[2][1] = ffma2(p, b1, acc[2][1]);
            p = bcast2(a0.w); acc[3][0] = ffma2(p, b0, acc[3][0]); acc[3][1] = ffma2(p, b1, acc[3][1]);
            p = bcast2(a1.x); acc[4][0] = ffma2(p, b0, acc[4][0]); acc[4][1] = ffma2(p, b1, acc[4][1]);
            p = bcast2(a1.y); acc[5][0] = ffma2(p, b0, acc[5][0]); acc[5][1] = ffma2(p, b1, acc[5][1]);
            p = bcast2(a1.z); acc[6][0] = ffma2(p, b0, acc[6][0]); acc[6][1] = ffma2(p, b1, acc[6][1]);
            p = bcast2(a1.w); acc[7][0] = ffma2(p, b0, acc[7][0]); acc[7][1] = ffma2(p, b1, acc[7][1]);
        }
        __syncthreads();
    }

    // epilogue: residual add + store
#pragma unroll
    for (int i = 0; i < 8; i++) {
        int row = m0 + ty * 8 + i;
        const float* hp = h + (size_t)row * INDIM + n0 + tx * 4;
        float4 hv = *(const float4*)hp;
        float a, b, cc, d;
        asm("mov.b64 {%0, %1}, %2;" : "=f"(a), "=f"(b) : "l"(acc[i][0]));
        asm("mov.b64 {%0, %1}, %2;" : "=f"(cc), "=f"(d) : "l"(acc[i][1]));
        float4 o;
        o.x = hv.x + a; o.y = hv.y + b; o.z = hv.z + cc; o.w = hv.w + d;
        *(float4*)(out + (size_t)row * INDIM + n0 + tx * 4) = o;
    }
}

// ======================================================================
extern "C" void kernel_launch(void* const* d_in, const int* in_sizes, int n_in,
                              void* d_out, int out_size) {
    const float* h     = (const float*)d_in[0];
    const float* W_y   = (const float*)d_in[1];
    const float* W_q   = (const float*)d_in[2];
    const float* W_k   = (const float*)d_in[3];
    const float* w_b   = (const float*)d_in[4];
    const float* W_out = (const float*)d_in[5];
    const float* sW_y  = (const float*)d_in[6];
    const float* sW_q  = (const float*)d_in[7];
    const float* sW_k  = (const float*)d_in[8];
    const float* sw_b  = (const float*)d_in[9];
    const float* F0    = (const float*)d_in[10];
    float* out = (float*)d_out;

    // 1) x = softmax(h) over D (rows = T*B*H = 262144, 8 rows per block)
    softmax_x_kernel<<<(TT * BB * NH) / 8, 256>>>(h);

    // 2) recurrence: one CTA per (b,h)
    srwm_kernel<<<BB * NH, 224>>>(W_y, W_q, W_k, w_b, sW_y, sW_q, sW_k, sw_b, F0);

    // 3) output projection + residual
    dim3 ggrid((TT * BB) / GBM, INDIM / GBN);
    out_gemm_kernel<<<ggrid, 256>>>(W_out, h, out);
}

// round 4
// speedup vs baseline: 1.7496x; 1.7496x over previous
#include <cuda_runtime.h>
#include <cuda_bf16.h>
#include <cstdint>

// Problem constants
#define TT   1024
#define BB   32
#define NH   8
#define DD   32
#define YD   97
#define INDIM 256          // NH*DD
#define ROWSTRIDE 8192     // BB*INDIM

typedef unsigned long long u64;

// -------- scratch (device globals; no allocation allowed) ----------
__device__ float g_fwm[(size_t)TT * BB * INDIM];   // FWM output pre-GEMM, 33.5 MB

// -------- packed f32x2 helpers ----------
__device__ __forceinline__ u64 ffma2(u64 a, u64 b, u64 c) {
    u64 d;
    asm("fma.rn.f32x2 %0, %1, %2, %3;" : "=l"(d) : "l"(a), "l"(b), "l"(c));
    return d;
}
__device__ __forceinline__ u64 add2(u64 a, u64 b) {
    u64 d;
    asm("add.rn.f32x2 %0, %1, %2;" : "=l"(d) : "l"(a), "l"(b));
    return d;
}
__device__ __forceinline__ u64 pack2(float a, float b) {
    u64 r;
    asm("mov.b64 %0, {%1, %2};" : "=l"(r) : "f"(a), "f"(b));
    return r;
}
__device__ __forceinline__ u64 bcast2(float a) {
    u64 r;
    asm("mov.b64 %0, {%1, %1};" : "=l"(r) : "f"(a));
    return r;
}
__device__ __forceinline__ float hsum2(u64 v) {
    float a, b;
    asm("mov.b64 {%0, %1}, %2;" : "=f"(a), "=f"(b) : "l"(v));
    return a + b;
}
__device__ __forceinline__ u64 lds2(const float* p) {
    return *(const u64*)p;   // LDS.64, requires 8B alignment
}

// -------- warp sum reduction ----------
__device__ __forceinline__ float wsum(float v) {
#pragma unroll
    for (int o = 16; o; o >>= 1) v += __shfl_xor_sync(0xffffffffu, v, o);
    return v;
}

// -------- dot(x[0:32], column) with 4 packed accumulators --------
__device__ __forceinline__ float dot32(const float* __restrict__ xp, const u64* c) {
    u64 a0 = 0ull, a1 = 0ull, a2 = 0ull, a3 = 0ull;
#pragma unroll
    for (int i = 0; i < 4; i++) {
        a0 = ffma2(lds2(xp + 8 * i),     c[4 * i],     a0);
        a1 = ffma2(lds2(xp + 8 * i + 2), c[4 * i + 1], a1);
        a2 = ffma2(lds2(xp + 8 * i + 4), c[4 * i + 2], a2);
        a3 = ffma2(lds2(xp + 8 * i + 6), c[4 * i + 3], a3);
    }
    return hsum2(add2(add2(a0, a1), add2(a2, a3)));
}

// ======================================================================
// Kernel 1: fused softmax(h) + SRWM + fast-weight-memory recurrence.
// One CTA per (b,h). 7 warps, columns register-resident.
// Single __syncthreads per step (double-buffered broadcast vectors).
// ======================================================================
__global__ __launch_bounds__(224, 2)
void srwm_kernel(const float* __restrict__ h,
                 const float* __restrict__ W_y, const float* __restrict__ W_q,
                 const float* __restrict__ W_k, const float* __restrict__ w_b,
                 const float* __restrict__ sW_y, const float* __restrict__ sW_q,
                 const float* __restrict__ sW_k, const float* __restrict__ sw_b,
                 const float* __restrict__ F0) {
    __shared__ __align__(16) float xs[2][DD];
    __shared__ __align__(16) float q_s[2][DD], k_s[2][DD];
    __shared__ __align__(16) float fq_s[2][DD], fk_s[2][DD], fv_s[2][DD];
    __shared__ __align__(16) float beta_s[2][4];
    __shared__ float fb_s[2];

    const int bh   = blockIdx.x;           // b*NH + h
    const int hh   = bh & (NH - 1);
    const int tid  = threadIdx.x;
    const int warp = tid >> 5;
    const int lane = tid & 31;

    // ---- role / column assignment ----
    // role 0: Wy col e (0..96)   role 1: wb col e (0..3)
    // role 2: Wq col e           role 3: Wk col e
    // role 4: F  col e (warp 6; also h softmax staging + out STG)
    // role 5: idle (warp 3 lanes 5..31)
    int role = 5, e = 0;
    if (warp < 3)            { role = 0; e = warp * 32 + lane; }
    else if (warp == 3) {
        if (lane == 0)       { role = 0; e = 96; }
        else if (lane <= 4)  { role = 1; e = lane - 1; }
    }
    else if (warp == 4)      { role = 2; e = lane; }
    else if (warp == 5)      { role = 3; e = lane; }
    else                     { role = 4; e = lane; }

    const int bidx = (role == 0) ? 0 : (role == 2) ? 1 : (role == 3) ? 2 : 3;

    // ---- initial column load (state + broadcast weight) ----
    const float* sp = nullptr;
    const float* wp = nullptr;
    int stride = 0;
    switch (role) {
        case 0: sp = sW_y + (size_t)bh * DD * YD + e; wp = W_y + (size_t)hh * DD * YD + e; stride = YD; break;
        case 1: sp = sw_b + (size_t)bh * DD * 4  + e; wp = w_b + (size_t)hh * DD * 4  + e; stride = 4;  break;
        case 2: sp = sW_q + (size_t)bh * DD * DD + e; wp = W_q + (size_t)hh * DD * DD + e; stride = DD; break;
        case 3: sp = sW_k + (size_t)bh * DD * DD + e; wp = W_k + (size_t)hh * DD * DD + e; stride = DD; break;
        case 4: sp = F0   + (size_t)bh * DD * DD + e;                                       stride = DD; break;
        default: break;
    }
    u64 c[16];
    if (role <= 4) {
#pragma unroll
        for (int i = 0; i < 16; i++) {
            float v0 = sp[(2 * i)     * stride];
            float v1 = sp[(2 * i + 1) * stride];
            if (wp) { v0 += wp[(2 * i) * stride]; v1 += wp[(2 * i + 1) * stride]; }
            c[i] = pack2(v0, v1);
        }
    } else {
#pragma unroll
        for (int i = 0; i < 16; i++) c[i] = 0ull;
    }

    // ---- prologue: warp 6 computes x_0 = softmax(h_0), prefetches h_1 ----
    const float* hrow = h + (size_t)bh * DD + lane;
    float xreg = 0.0f;
    float* gout = g_fwm + (size_t)bh * DD + lane;
    if (role == 4) {
        float p = __expf(hrow[0]);
        float s = wsum(p);
        xs[0][lane] = __fdividef(p, s);
        xreg = hrow[ROWSTRIDE];
    }
    __syncthreads();

    // ---- peeled iteration t = 0: phase2 only ----
    if (role <= 3) {
        float yv = dot32(xs[0], c);
        if (warp == 0)       { float p = __expf(yv); float s = wsum(p); fq_s[0][lane] = __fdividef(p, s); }
        else if (warp == 1)  { float p = __expf(yv); float s = wsum(p); fk_s[0][lane] = __fdividef(p, s); }
        else if (warp == 2)  { fv_s[0][lane] = yv; }
        else if (warp == 3)  { float sg = __fdividef(1.0f, 1.0f + __expf(-yv));
                               if (role == 0) fb_s[0] = sg; else beta_s[0][e] = sg; }
        else if (warp == 4)  { float p = __expf(yv); float s = wsum(p); q_s[0][lane] = __fdividef(p, s); }
        else                 { float p = __expf(yv); float s = wsum(p); k_s[0][lane] = __fdividef(p, s); }
    } else if (role == 4) {
        float p = __expf(xreg);
        float s = wsum(p);
        xs[1][lane] = __fdividef(p, s);
        xreg = hrow[(size_t)2 * ROWSTRIDE];
    }
    __syncthreads();

    // ================= time loop: one barrier per step =================
    for (int t = 1; t < TT; t++) {
        const int pm = (t - 1) & 1;   // buffers produced at step t-1
        const int pc = t & 1;         // buffers produced at step t

        if (role <= 3) {
            // ---- phase 3 of step t-1: SRWM update ----
            {
                const float bi = beta_s[pm][bidx];
                const float* qp = q_s[pm];
                const float* kp = k_s[pm];
                u64 vq0 = 0ull, vq1 = 0ull, vk0 = 0ull, vk1 = 0ull;
                u64 kc[16];
#pragma unroll
                for (int i = 0; i < 16; i += 2) {
                    u64 q2 = lds2(qp + 2 * i);
                    u64 k2 = lds2(kp + 2 * i);
                    kc[i] = k2;
                    vq0 = ffma2(q2, c[i], vq0);
                    vk0 = ffma2(k2, c[i], vk0);
                    u64 q3 = lds2(qp + 2 * i + 2);
                    u64 k3 = lds2(kp + 2 * i + 2);
                    kc[i + 1] = k3;
                    vq1 = ffma2(q3, c[i + 1], vq1);
                    vk1 = ffma2(k3, c[i + 1], vk1);
                }
                float delta = bi * (hsum2(add2(vq0, vq1)) - hsum2(add2(vk0, vk1)));
                u64 d2 = bcast2(delta);
#pragma unroll
                for (int i = 0; i < 16; i++) c[i] = ffma2(kc[i], d2, c[i]);
            }
            // ---- phase 2 of step t: matvec + activations ----
            {
                float yv = dot32(xs[pc], c);
                if (warp == 0)       { float p = __expf(yv); float s = wsum(p); fq_s[pc][lane] = __fdividef(p, s); }
                else if (warp == 1)  { float p = __expf(yv); float s = wsum(p); fk_s[pc][lane] = __fdividef(p, s); }
                else if (warp == 2)  { fv_s[pc][lane] = yv; }
                else if (warp == 3)  { float sg = __fdividef(1.0f, 1.0f + __expf(-yv));
                                       if (role == 0) fb_s[pc] = sg; else beta_s[pc][e] = sg; }
                else if (warp == 4)  { float p = __expf(yv); float s = wsum(p); q_s[pc][lane] = __fdividef(p, s); }
                else                 { float p = __expf(yv); float s = wsum(p); k_s[pc][lane] = __fdividef(p, s); }
            }
        } else if (role == 4) {
            // ---- FWM step t-1 ----
            {
                const float* fqp = fq_s[pm];
                const float* fkp = fk_s[pm];
                u64 vo0 = 0ull, vo1 = 0ull, oq0 = 0ull, oq1 = 0ull, ss0 = 0ull, ss1 = 0ull;
                u64 fkc[16];
#pragma unroll
                for (int i = 0; i < 16; i += 2) {
                    u64 fq2 = lds2(fqp + 2 * i);
                    u64 fk2 = lds2(fkp + 2 * i);
                    fkc[i] = fk2;
                    vo0 = ffma2(fk2, c[i], vo0);
                    oq0 = ffma2(fq2, c[i], oq0);
                    ss0 = ffma2(fq2, fk2, ss0);
                    u64 fq3 = lds2(fqp + 2 * i + 2);
                    u64 fk3 = lds2(fkp + 2 * i + 2);
                    fkc[i + 1] = fk3;
                    vo1 = ffma2(fk3, c[i + 1], vo1);
                    oq1 = ffma2(fq3, c[i + 1], oq1);
                    ss1 = ffma2(fq3, fk3, ss1);
                }
                float vold = hsum2(add2(vo0, vo1));
                float outq = hsum2(add2(oq0, oq1));
                float sqk  = hsum2(add2(ss0, ss1));
                float delta = fb_s[pm] * (fv_s[pm][lane] - vold);
                u64 d2 = bcast2(delta);
#pragma unroll
                for (int i = 0; i < 16; i++) c[i] = ffma2(fkc[i], d2, c[i]);
                gout[(size_t)(t - 1) * ROWSTRIDE] = outq + delta * sqk;
            }
            // ---- stage x_{t+1}, prefetch h_{t+2} ----
            {
                float p = __expf(xreg);
                float s = wsum(p);
                xs[(t + 1) & 1][lane] = __fdividef(p, s);
                xreg = (t + 2 < TT) ? hrow[(size_t)(t + 2) * ROWSTRIDE] : 0.0f;
            }
        }
        __syncthreads();
    }

    // ---- epilogue: FWM step TT-1 ----
    if (role == 4) {
        const int pm = (TT - 1) & 1;
        const float* fqp = fq_s[pm];
        const float* fkp = fk_s[pm];
        u64 vo0 = 0ull, vo1 = 0ull, oq0 = 0ull, oq1 = 0ull, ss0 = 0ull, ss1 = 0ull;
#pragma unroll
        for (int i = 0; i < 16; i += 2) {
            u64 fq2 = lds2(fqp + 2 * i);
            u64 fk2 = lds2(fkp + 2 * i);
            vo0 = ffma2(fk2, c[i], vo0);
            oq0 = ffma2(fq2, c[i], oq0);
            ss0 = ffma2(fq2, fk2, ss0);
            u64 fq3 = lds2(fqp + 2 * i + 2);
            u64 fk3 = lds2(fkp + 2 * i + 2);
            vo1 = ffma2(fk3, c[i + 1], vo1);
            oq1 = ffma2(fq3, c[i + 1], oq1);
            ss1 = ffma2(fq3, fk3, ss1);
        }
        float vold = hsum2(add2(vo0, vo1));
        float outq = hsum2(add2(oq0, oq1));
        float sqk  = hsum2(add2(ss0, ss1));
        float delta = fb_s[pm] * (fv_s[pm][lane] - vold);
        gout[(size_t)(TT - 1) * ROWSTRIDE] = outq + delta * sqk;
    }
}

// ======================================================================
// Kernel 2: out = h + g_fwm @ W_out^T    (M=32768, N=256, K=256)
// BM=128, BN=64, BK=16, 256 threads, thread tile 8x4 (f32x2 packed)
// ======================================================================
#define GBM 128
#define GBN 64
#define GBK 16

__global__ __launch_bounds__(256)
void out_gemm_kernel(const float* __restrict__ W,   // W_out [n][k], 256x256
                     const float* __restrict__ h,
                     float* __restrict__ out) {
    __shared__ float As[GBK][GBM];
    __shared__ float Bs[GBK][GBN];

    const int tid = threadIdx.x;
    const int m0  = blockIdx.x * GBM;
    const int n0  = blockIdx.y * GBN;
    const int ty  = tid >> 4;    // 0..15 -> m sub-tile
    const int tx  = tid & 15;    // 0..15 -> n sub-tile

    u64 acc[8][2];
#pragma unroll
    for (int i = 0; i < 8; i++) { acc[i][0] = 0ull; acc[i][1] = 0ull; }

    for (int kt = 0; kt < INDIM; kt += GBK) {
        // load A tile (g_fwm) 128x16 : 2 float4 per thread
#pragma unroll
        for (int r = 0; r < 2; r++) {
            int id  = tid + r * 256;
            int row = id >> 2;
            int kv  = (id & 3) * 4;
            float4 v = *(const float4*)(g_fwm + (size_t)(m0 + row) * INDIM + kt + kv);
            As[kv + 0][row] = v.x; As[kv + 1][row] = v.y;
            As[kv + 2][row] = v.z; As[kv + 3][row] = v.w;
        }
        // load B tile (W_out) 64x16 : 1 float4 per thread
        {
            int row = tid >> 2;
            int kv  = (tid & 3) * 4;
            float4 v = *(const float4*)(W + (size_t)(n0 + row) * INDIM + kt + kv);
            Bs[kv + 0][row] = v.x; Bs[kv + 1][row] = v.y;
            Bs[kv + 2][row] = v.z; Bs[kv + 3][row] = v.w;
        }
        __syncthreads();

#pragma unroll
        for (int k = 0; k < GBK; k++) {
            float4 a0 = *(const float4*)&As[k][ty * 8];
            float4 a1 = *(const float4*)&As[k][ty * 8 + 4];
            u64 b0 = lds2(&Bs[k][tx * 4]);
            u64 b1 = lds2(&Bs[k][tx * 4 + 2]);
            u64 p;
            p = bcast2(a0.x); acc[0][0] = ffma2(p, b0, acc[0][0]); acc[0][1] = ffma2(p, b1, acc[0][1]);
            p = bcast2(a0.y); acc[1][0] = ffma2(p, b0, acc[1][0]); acc[1][1] = ffma2(p, b1, acc[1][1]);
            p = bcast2(a0.z); acc[2][0] = ffma2(p, b0, acc[2][0]); acc[2][1] = ffma2(p, b1, acc[2][1]);
            p = bcast2(a0.w); acc[3][0] = ffma2(p, b0, acc[3][0]); acc[3][1] = ffma2(p, b1, acc[3][1]);
            p = bcast2(a1.x); acc[4][0] = ffma2(p, b0, acc[4][0]); acc[4][1] = ffma2(p, b1, acc[4][1]);
            p = bcast2(a1.y); acc[5][0] = ffma2(p, b0, acc[5][0]); acc[5][1] = ffma2(p, b1, acc[5][1]);
            p = bcast2(a1.z); acc[6][0] = ffma2(p, b0, acc[6][0]); acc[6][1] = ffma2(p, b1, acc[6][1]);
            p = bcast2(a1.w); acc[7][0] = ffma2(p, b0, acc[7][0]); acc[7][1] = ffma2(p, b1, acc[7][1]);
        }
        __syncthreads();
    }

    // epilogue: residual add + store
#pragma unroll
    for (int i = 0; i < 8; i++) {
        int row = m0 + ty * 8 + i;
        const float* hp = h + (size_t)row * INDIM + n0 + tx * 4;
        float4 hv = *(const float4*)hp;
        float a, b, cc, d;
        asm("mov.b64 {%0, %1}, %2;" : "=f"(a), "=f"(b) : "l"(acc[i][0]));
        asm("mov.b64 {%0, %1}, %2;" : "=f"(cc), "=f"(d) : "l"(acc[i][1]));
        float4 o;
        o.x = hv.x + a; o.y = hv.y + b; o.z = hv.z + cc; o.w = hv.w + d;
        *(float4*)(out + (size_t)row * INDIM + n0 + tx * 4) = o;
    }
}

// ======================================================================
extern "C" void kernel_launch(void* const* d_in, const int* in_sizes, int n_in,
                              void* d_out, int out_size) {
    const float* h     = (const float*)d_in[0];
    const float* W_y   = (const float*)d_in[1];
    const float* W_q   = (const float*)d_in[2];
    const float* W_k   = (const float*)d_in[3];
    const float* w_b   = (const float*)d_in[4];
    const float* W_out = (const float*)d_in[5];
    const float* sW_y  = (const float*)d_in[6];
    const float* sW_q  = (const float*)d_in[7];
    const float* sW_k  = (const float*)d_in[8];
    const float* sw_b  = (const float*)d_in[9];
    const float* F0    = (const float*)d_in[10];
    float* out = (float*)d_out;

    // 1) fused recurrence (h softmax computed in-kernel): one CTA per (b,h)
    srwm_kernel<<<BB * NH, 224>>>(h, W_y, W_q, W_k, w_b, sW_y, sW_q, sW_k, sw_b, F0);

    // 2) output projection + residual
    dim3 ggrid((TT * BB) / GBM, INDIM / GBN);
    out_gemm_kernel<<<ggrid, 256>>>(W_out, h, out);
}

// round 5
// speedup vs baseline: 1.7957x; 1.0263x over previous
#include <cuda_runtime.h>
#include <cuda_bf16.h>
#include <cstdint>

// Problem constants
#define TT   1024
#define BB   32
#define NH   8
#define DD   32
#define YD   97
#define INDIM 256          // NH*DD
#define ROWSTRIDE 8192     // BB*INDIM

typedef unsigned long long u64;

// -------- scratch (device globals; no allocation allowed) ----------
__device__ float g_fwm[(size_t)TT * BB * INDIM];   // FWM output pre-GEMM, 33.5 MB

// -------- packed f32x2 helpers ----------
__device__ __forceinline__ u64 ffma2(u64 a, u64 b, u64 c) {
    u64 d;
    asm("fma.rn.f32x2 %0, %1, %2, %3;" : "=l"(d) : "l"(a), "l"(b), "l"(c));
    return d;
}
__device__ __forceinline__ u64 add2(u64 a, u64 b) {
    u64 d;
    asm("add.rn.f32x2 %0, %1, %2;" : "=l"(d) : "l"(a), "l"(b));
    return d;
}
__device__ __forceinline__ u64 pack2(float a, float b) {
    u64 r;
    asm("mov.b64 %0, {%1, %2};" : "=l"(r) : "f"(a), "f"(b));
    return r;
}
__device__ __forceinline__ u64 bcast2(float a) {
    u64 r;
    asm("mov.b64 %0, {%1, %1};" : "=l"(r) : "f"(a));
    return r;
}
__device__ __forceinline__ float hsum2(u64 v) {
    float a, b;
    asm("mov.b64 {%0, %1}, %2;" : "=f"(a), "=f"(b) : "l"(v));
    return a + b;
}
__device__ __forceinline__ u64 lds2(const float* p) {
    return *(const u64*)p;   // LDS.64
}

// float4 viewed as two packed f32x2
union f4u {
    float4 f;
    u64    u[2];
};
__device__ __forceinline__ f4u ld4(const float* p) {
    f4u r;
    r.f = *(const float4*)p;   // LDS.128
    return r;
}

// -------- warp sum reduction ----------
__device__ __forceinline__ float wsum(float v) {
#pragma unroll
    for (int o = 16; o; o >>= 1) v += __shfl_xor_sync(0xffffffffu, v, o);
    return v;
}

// -------- dot(x[0:32], column) via 8 LDS.128 + 16 FFMA2 --------
__device__ __forceinline__ float dot32v(const float* __restrict__ xp, const u64* c) {
    u64 a0 = 0ull, a1 = 0ull, a2 = 0ull, a3 = 0ull;
#pragma unroll
    for (int i = 0; i < 4; i++) {
        f4u x0 = ld4(xp + 8 * i);
        f4u x1 = ld4(xp + 8 * i + 4);
        a0 = ffma2(x0.u[0], c[4 * i],     a0);
        a1 = ffma2(x0.u[1], c[4 * i + 1], a1);
        a2 = ffma2(x1.u[0], c[4 * i + 2], a2);
        a3 = ffma2(x1.u[1], c[4 * i + 3], a3);
    }
    return hsum2(add2(add2(a0, a1), add2(a2, a3)));
}

// ======================================================================
// Kernel 1: fused softmax(h) + SRWM + FWM recurrence. One CTA per (b,h).
// 7 warps, state columns register-resident, LDS.128 broadcast reads.
// One __syncthreads per step (double-buffered broadcast vectors).
// ======================================================================
__global__ __launch_bounds__(224, 2)
void srwm_kernel(const float* __restrict__ h,
                 const float* __restrict__ W_y, const float* __restrict__ W_q,
                 const float* __restrict__ W_k, const float* __restrict__ w_b,
                 const float* __restrict__ sW_y, const float* __restrict__ sW_q,
                 const float* __restrict__ sW_k, const float* __restrict__ sw_b,
                 const float* __restrict__ F0) {
    __shared__ __align__(16) float xs[2][DD];
    __shared__ __align__(16) float q_s[2][DD], k_s[2][DD];
    __shared__ __align__(16) float fq_s[2][DD], fk_s[2][DD], fv_s[2][DD];
    __shared__ __align__(16) float beta_s[2][4];
    __shared__ float fb_s[2];

    const int bh   = blockIdx.x;           // b*NH + h
    const int hh   = bh & (NH - 1);
    const int tid  = threadIdx.x;
    const int warp = tid >> 5;
    const int lane = tid & 31;

    // ---- role / column assignment ----
    int role = 5, e = 0;
    if (warp < 3)            { role = 0; e = warp * 32 + lane; }
    else if (warp == 3) {
        if (lane == 0)       { role = 0; e = 96; }
        else if (lane <= 4)  { role = 1; e = lane - 1; }
    }
    else if (warp == 4)      { role = 2; e = lane; }
    else if (warp == 5)      { role = 3; e = lane; }
    else                     { role = 4; e = lane; }

    const int bidx = (role == 0) ? 0 : (role == 2) ? 1 : (role == 3) ? 2 : 3;

    // ---- initial column load (state + broadcast weight) ----
    const float* sp = nullptr;
    const float* wp = nullptr;
    int stride = 0;
    switch (role) {
        case 0: sp = sW_y + (size_t)bh * DD * YD + e; wp = W_y + (size_t)hh * DD * YD + e; stride = YD; break;
        case 1: sp = sw_b + (size_t)bh * DD * 4  + e; wp = w_b + (size_t)hh * DD * 4  + e; stride = 4;  break;
        case 2: sp = sW_q + (size_t)bh * DD * DD + e; wp = W_q + (size_t)hh * DD * DD + e; stride = DD; break;
        case 3: sp = sW_k + (size_t)bh * DD * DD + e; wp = W_k + (size_t)hh * DD * DD + e; stride = DD; break;
        case 4: sp = F0   + (size_t)bh * DD * DD + e;                                       stride = DD; break;
        default: break;
    }
    u64 c[16];
    if (role <= 4) {
#pragma unroll
        for (int i = 0; i < 16; i++) {
            float v0 = sp[(2 * i)     * stride];
            float v1 = sp[(2 * i + 1) * stride];
            if (wp) { v0 += wp[(2 * i) * stride]; v1 += wp[(2 * i + 1) * stride]; }
            c[i] = pack2(v0, v1);
        }
    } else {
#pragma unroll
        for (int i = 0; i < 16; i++) c[i] = 0ull;
    }

    // ---- prologue: warp 6 computes x_0 = softmax(h_0), prefetches h_1 ----
    const float* hrow = h + (size_t)bh * DD + lane;
    float xreg = 0.0f;
    float* gout = g_fwm + (size_t)bh * DD + lane;
    if (role == 4) {
        float p = __expf(hrow[0]);
        float s = wsum(p);
        xs[0][lane] = __fdividef(p, s);
        xreg = hrow[ROWSTRIDE];
    }
    __syncthreads();

    // ---- peeled iteration t = 0: phase2 only ----
    if (role <= 3) {
        float yv = dot32v(xs[0], c);
        if (warp == 0)       { float p = __expf(yv); float s = wsum(p); fq_s[0][lane] = __fdividef(p, s); }
        else if (warp == 1)  { float p = __expf(yv); float s = wsum(p); fk_s[0][lane] = __fdividef(p, s); }
        else if (warp == 2)  { fv_s[0][lane] = yv; }
        else if (warp == 3)  { float sg = __fdividef(1.0f, 1.0f + __expf(-yv));
                               if (role == 0) fb_s[0] = sg; else beta_s[0][e] = sg; }
        else if (warp == 4)  { float p = __expf(yv); float s = wsum(p); q_s[0][lane] = __fdividef(p, s); }
        else                 { float p = __expf(yv); float s = wsum(p); k_s[0][lane] = __fdividef(p, s); }
    } else if (role == 4) {
        float p = __expf(xreg);
        float s = wsum(p);
        xs[1][lane] = __fdividef(p, s);
        xreg = hrow[(size_t)2 * ROWSTRIDE];
    }
    __syncthreads();

    // ================= time loop: one barrier per step =================
    for (int t = 1; t < TT; t++) {
        const int pm = (t - 1) & 1;   // buffers produced at step t-1
        const int pc = t & 1;         // buffers produced at step t

        if (role <= 3) {
            // ---- phase 3 of step t-1: SRWM update (vectorized loads) ----
            {
                const float bi = beta_s[pm][bidx];
                const float* qp = q_s[pm];
                const float* kp = k_s[pm];
                f4u qv[8], kv[8];
#pragma unroll
                for (int i = 0; i < 8; i++) { qv[i] = ld4(qp + 4 * i); kv[i] = ld4(kp + 4 * i); }
                u64 vq0 = 0ull, vq1 = 0ull, vk0 = 0ull, vk1 = 0ull;
#pragma unroll
                for (int i = 0; i < 8; i++) {
                    vq0 = ffma2(qv[i].u[0], c[2 * i],     vq0);
                    vq1 = ffma2(qv[i].u[1], c[2 * i + 1], vq1);
                    vk0 = ffma2(kv[i].u[0], c[2 * i],     vk0);
                    vk1 = ffma2(kv[i].u[1], c[2 * i + 1], vk1);
                }
                float delta = bi * (hsum2(add2(vq0, vq1)) - hsum2(add2(vk0, vk1)));
                u64 d2 = bcast2(delta);
#pragma unroll
                for (int i = 0; i < 8; i++) {
                    c[2 * i]     = ffma2(kv[i].u[0], d2, c[2 * i]);
                    c[2 * i + 1] = ffma2(kv[i].u[1], d2, c[2 * i + 1]);
                }
            }
            // ---- phase 2 of step t: matvec + activations ----
            {
                float yv = dot32v(xs[pc], c);
                if (warp == 0)       { float p = __expf(yv); float s = wsum(p); fq_s[pc][lane] = __fdividef(p, s); }
                else if (warp == 1)  { float p = __expf(yv); float s = wsum(p); fk_s[pc][lane] = __fdividef(p, s); }
                else if (warp == 2)  { fv_s[pc][lane] = yv; }
                else if (warp == 3)  { float sg = __fdividef(1.0f, 1.0f + __expf(-yv));
                                       if (role == 0) fb_s[pc] = sg; else beta_s[pc][e] = sg; }
                else if (warp == 4)  { float p = __expf(yv); float s = wsum(p); q_s[pc][lane] = __fdividef(p, s); }
                else                 { float p = __expf(yv); float s = wsum(p); k_s[pc][lane] = __fdividef(p, s); }
            }
        } else if (role == 4) {
            // ---- FWM step t-1 ----
            {
                const float* fqp = fq_s[pm];
                const float* fkp = fk_s[pm];
                f4u fqv[8], fkv[8];
#pragma unroll
                for (int i = 0; i < 8; i++) { fqv[i] = ld4(fqp + 4 * i); fkv[i] = ld4(fkp + 4 * i); }
                u64 vo0 = 0ull, vo1 = 0ull, oq0 = 0ull, oq1 = 0ull, ss0 = 0ull, ss1 = 0ull;
#pragma unroll
                for (int i = 0; i < 8; i++) {
                    vo0 = ffma2(fkv[i].u[0], c[2 * i],     vo0);
                    vo1 = ffma2(fkv[i].u[1], c[2 * i + 1], vo1);
                    oq0 = ffma2(fqv[i].u[0], c[2 * i],     oq0);
                    oq1 = ffma2(fqv[i].u[1], c[2 * i + 1], oq1);
                    ss0 = ffma2(fqv[i].u[0], fkv[i].u[0],  ss0);
                    ss1 = ffma2(fqv[i].u[1], fkv[i].u[1],  ss1);
                }
                float vold = hsum2(add2(vo0, vo1));
                float outq = hsum2(add2(oq0, oq1));
                float sqk  = hsum2(add2(ss0, ss1));
                float delta = fb_s[pm] * (fv_s[pm][lane] - vold);
                u64 d2 = bcast2(delta);
#pragma unroll
                for (int i = 0; i < 8; i++) {
                    c[2 * i]     = ffma2(fkv[i].u[0], d2, c[2 * i]);
                    c[2 * i + 1] = ffma2(fkv[i].u[1], d2, c[2 * i + 1]);
                }
                gout[(size_t)(t - 1) * ROWSTRIDE] = outq + delta * sqk;
            }
            // ---- stage x_{t+1}, prefetch h_{t+2} ----
            {
                float p = __expf(xreg);
                float s = wsum(p);
                xs[(t + 1) & 1][lane] = __fdividef(p, s);
                xreg = (t + 2 < TT) ? hrow[(size_t)(t + 2) * ROWSTRIDE] : 0.0f;
            }
        }
        __syncthreads();
    }

    // ---- epilogue: FWM step TT-1 ----
    if (role == 4) {
        const int pm = (TT - 1) & 1;
        const float* fqp = fq_s[pm];
        const float* fkp = fk_s[pm];
        f4u fqv[8], fkv[8];
#pragma unroll
        for (int i = 0; i < 8; i++) { fqv[i] = ld4(fqp + 4 * i); fkv[i] = ld4(fkp + 4 * i); }
        u64 vo0 = 0ull, vo1 = 0ull, oq0 = 0ull, oq1 = 0ull, ss0 = 0ull, ss1 = 0ull;
#pragma unroll
        for (int i = 0; i < 8; i++) {
            vo0 = ffma2(fkv[i].u[0], c[2 * i],     vo0);
            vo1 = ffma2(fkv[i].u[1], c[2 * i + 1], vo1);
            oq0 = ffma2(fqv[i].u[0], c[2 * i],     oq0);
            oq1 = ffma2(fqv[i].u[1], c[2 * i + 1], oq1);
            ss0 = ffma2(fqv[i].u[0], fkv[i].u[0],  ss0);
            ss1 = ffma2(fqv[i].u[1], fkv[i].u[1],  ss1);
        }
        float vold = hsum2(add2(vo0, vo1));
        float outq = hsum2(add2(oq0, oq1));
        float sqk  = hsum2(add2(ss0, ss1));
        float delta = fb_s[pm] * (fv_s[pm][lane] - vold);
        gout[(size_t)(TT - 1) * ROWSTRIDE] = outq + delta * sqk;
    }
}

// ======================================================================
// Kernel 2: out = h + g_fwm @ W_out^T    (M=32768, N=256, K=256)
// BM=128, BN=64, BK=32, 256 threads, 8x4 f32x2 thread tile,
// 2-stage double-buffered smem, one __syncthreads per k-tile.
// ======================================================================
#define GBM 128
#define GBN 64
#define GBK 32
#define ALDA (GBM + 4)   // padded row stride (floats): conflict-free scatter STS
#define BLDA (GBN + 4)

__global__ __launch_bounds__(256)
void out_gemm_kernel(const float* __restrict__ W,   // W_out [n][k], 256x256
                     const float* __restrict__ h,
                     float* __restrict__ out) {
    __shared__ __align__(16) float As[2][GBK][ALDA];
    __shared__ __align__(16) float Bs[2][GBK][BLDA];

    const int tid = threadIdx.x;
    const int m0  = blockIdx.x * GBM;
    const int n0  = blockIdx.y * GBN;
    const int ty  = tid >> 4;    // 0..15 -> m sub-tile (8 rows)
    const int tx  = tid & 15;    // 0..15 -> n sub-tile (4 cols)

    // A: 128 rows x 32 k = 1024 float4 -> 4 per thread
    const int a_row = tid >> 3;          // 0..31 base rows (x4 groups)
    const int a_kv  = (tid & 7) * 4;     // k offset 0..28
    // B: 64 rows x 32 k = 512 float4 -> 2 per thread
    const int b_row = tid >> 3;
    const int b_kv  = (tid & 7) * 4;

    u64 acc[8][2];
#pragma unroll
    for (int i = 0; i < 8; i++) { acc[i][0] = 0ull; acc[i][1] = 0ull; }

    const int NT = INDIM / GBK;   // 8 k-tiles

    float4 ar[4], br[2];
    // --- prologue: load tile 0 ---
#pragma unroll
    for (int r = 0; r < 4; r++)
        ar[r] = *(const float4*)(g_fwm + (size_t)(m0 + a_row + r * 32) * INDIM + a_kv);
#pragma unroll
    for (int r = 0; r < 2; r++)
        br[r] = *(const float4*)(W + (size_t)(n0 + b_row + r * 32) * INDIM + b_kv);
#pragma unroll
    for (int r = 0; r < 4; r++) {
        int row = a_row + r * 32;
        As[0][a_kv + 0][row] = ar[r].x; As[0][a_kv + 1][row] = ar[r].y;
        As[0][a_kv + 2][row] = ar[r].z; As[0][a_kv + 3][row] = ar[r].w;
    }
#pragma unroll
    for (int r = 0; r < 2; r++) {
        int row = b_row + r * 32;
        Bs[0][b_kv + 0][row] = br[r].x; Bs[0][b_kv + 1][row] = br[r].y;
        Bs[0][b_kv + 2][row] = br[r].z; Bs[0][b_kv + 3][row] = br[r].w;
    }
    __syncthreads();

    for (int kt = 0; kt < NT; kt++) {
        const int s = kt & 1;
        // prefetch next tile into registers
        if (kt + 1 < NT) {
            const int ko = (kt + 1) * GBK;
#pragma unroll
            for (int r = 0; r < 4; r++)
                ar[r] = *(const float4*)(g_fwm + (size_t)(m0 + a_row + r * 32) * INDIM + ko + a_kv);
#pragma unroll
            for (int r = 0; r < 2; r++)
                br[r] = *(const float4*)(W + (size_t)(n0 + b_row + r * 32) * INDIM + ko + b_kv);
        }
        // compute on stage s
#pragma unroll
        for (int k = 0; k < GBK; k++) {
            f4u a0 = ld4(&As[s][k][ty * 8]);
            f4u a1 = ld4(&As[s][k][ty * 8 + 4]);
            f4u b  = ld4(&Bs[s][k][tx * 4]);
            u64 p;
            float av[8];
            av[0] = a0.f.x; av[1] = a0.f.y; av[2] = a0.f.z; av[3] = a0.f.w;
            av[4] = a1.f.x; av[5] = a1.f.y; av[6] = a1.f.z; av[7] = a1.f.w;
#pragma unroll
            for (int i = 0; i < 8; i++) {
                p = bcast2(av[i]);
                acc[i][0] = ffma2(p, b.u[0], acc[i][0]);
                acc[i][1] = ffma2(p, b.u[1], acc[i][1]);
            }
        }
        // store prefetched tile into the other stage
        if (kt + 1 < NT) {
            const int d = s ^ 1;
#pragma unroll
            for (int r = 0; r < 4; r++) {
                int row = a_row + r * 32;
                As[d][a_kv + 0][row] = ar[r].x; As[d][a_kv + 1][row] = ar[r].y;
                As[d][a_kv + 2][row] = ar[r].z; As[d][a_kv + 3][row] = ar[r].w;
            }
#pragma unroll
            for (int r = 0; r < 2; r++) {
                int row = b_row + r * 32;
                Bs[d][b_kv + 0][row] = br[r].x; Bs[d][b_kv + 1][row] = br[r].y;
                Bs[d][b_kv + 2][row] = br[r].z; Bs[d][b_kv + 3][row] = br[r].w;
            }
            __syncthreads();
        }
    }

    // epilogue: residual add + store
#pragma unroll
    for (int i = 0; i < 8; i++) {
        int row = m0 + ty * 8 + i;
        const float* hp = h + (size_t)row * INDIM + n0 + tx * 4;
        float4 hv = *(const float4*)hp;
        float a, b, cc, d;
        asm("mov.b64 {%0, %1}, %2;" : "=f"(a), "=f"(b) : "l"(acc[i][0]));
        asm("mov.b64 {%0, %1}, %2;" : "=f"(cc), "=f"(d) : "l"(acc[i][1]));
        float4 o;
        o.x = hv.x + a; o.y = hv.y + b; o.z = hv.z + cc; o.w = hv.w + d;
        *(float4*)(out + (size_t)row * INDIM + n0 + tx * 4) = o;
    }
}

// ======================================================================
extern "C" void kernel_launch(void* const* d_in, const int* in_sizes, int n_in,
                              void* d_out, int out_size) {
    const float* h     = (const float*)d_in[0];
    const float* W_y   = (const float*)d_in[1];
    const float* W_q   = (const float*)d_in[2];
    const float* W_k   = (const float*)d_in[3];
    const float* w_b   = (const float*)d_in[4];
    const float* W_out = (const float*)d_in[5];
    const float* sW_y  = (const float*)d_in[6];
    const float* sW_q  = (const float*)d_in[7];
    const float* sW_k  = (const float*)d_in[8];
    const float* sw_b  = (const float*)d_in[9];
    const float* F0    = (const float*)d_in[10];
    float* out = (float*)d_out;

    // 1) fused recurrence (h softmax computed in-kernel): one CTA per (b,h)
    srwm_kernel<<<BB * NH, 224>>>(h, W_y, W_q, W_k, w_b, sW_y, sW_q, sW_k, sw_b, F0);

    // 2) output projection + residual
    dim3 ggrid((TT * BB) / GBM, INDIM / GBN);
    out_gemm_kernel<<<ggrid, 256>>>(W_out, h, out);
}

// round 8
// speedup vs baseline: 1.8993x; 1.0577x over previous
#include <cuda_runtime.h>
#include <cuda_bf16.h>
#include <cstdint>

// Problem constants
#define TT   1024
#define BB   32
#define NH   8
#define DD   32
#define YD   97
#define INDIM 256          // NH*DD
#define ROWSTRIDE 8192     // BB*INDIM

typedef unsigned long long u64;

// -------- scratch (device globals; no allocation allowed) ----------
__device__ float g_fwm[(size_t)TT * BB * INDIM];   // FWM output pre-GEMM, 33.5 MB

// -------- packed f32x2 helpers ----------
__device__ __forceinline__ u64 ffma2(u64 a, u64 b, u64 c) {
    u64 d;
    asm("fma.rn.f32x2 %0, %1, %2, %3;" : "=l"(d) : "l"(a), "l"(b), "l"(c));
    return d;
}
__device__ __forceinline__ u64 add2(u64 a, u64 b) {
    u64 d;
    asm("add.rn.f32x2 %0, %1, %2;" : "=l"(d) : "l"(a), "l"(b));
    return d;
}
__device__ __forceinline__ u64 pack2(float a, float b) {
    u64 r;
    asm("mov.b64 %0, {%1, %2};" : "=l"(r) : "f"(a), "f"(b));
    return r;
}
__device__ __forceinline__ u64 bcast2(float a) {
    u64 r;
    asm("mov.b64 %0, {%1, %1};" : "=l"(r) : "f"(a));
    return r;
}
__device__ __forceinline__ float hsum2(u64 v) {
    float a, b;
    asm("mov.b64 {%0, %1}, %2;" : "=f"(a), "=f"(b) : "l"(v));
    return a + b;
}

// float4 viewed as two packed f32x2
union f4u {
    float4 f;
    u64    u[2];
};
__device__ __forceinline__ f4u ld4(const float* p) {
    f4u r;
    r.f = *(const float4*)p;   // LDS.128
    return r;
}

// -------- warp sum (5-round SHFL butterfly; f32 REDUX absent on sm_103) ----
__device__ __forceinline__ float wsum(float v) {
#pragma unroll
    for (int o = 16; o; o >>= 1) v += __shfl_xor_sync(0xffffffffu, v, o);
    return v;
}

// -------- dot(x[0:32], column) via 8 LDS.128 + 16 FFMA2 (peel only) --------
__device__ __forceinline__ float dot32v(const float* __restrict__ xp, const u64* c) {
    u64 a0 = 0ull, a1 = 0ull, a2 = 0ull, a3 = 0ull;
#pragma unroll
    for (int i = 0; i < 4; i++) {
        f4u x0 = ld4(xp + 8 * i);
        f4u x1 = ld4(xp + 8 * i + 4);
        a0 = ffma2(x0.u[0], c[4 * i],     a0);
        a1 = ffma2(x0.u[1], c[4 * i + 1], a1);
        a2 = ffma2(x1.u[0], c[4 * i + 2], a2);
        a3 = ffma2(x1.u[1], c[4 * i + 3], a3);
    }
    return hsum2(add2(add2(a0, a1), add2(a2, a3)));
}

// ======================================================================
// Kernel 1: fused softmax(h) + SRWM + FWM recurrence. One CTA per (b,h).
// Chain-minimized: y_t = x·c_old + delta·(x·k);  c += k·delta off-path.
// One barrier per step (double-buffered broadcast vectors).
// ======================================================================
__global__ __launch_bounds__(224, 2)
void srwm_kernel(const float* __restrict__ h,
                 const float* __restrict__ W_y, const float* __restrict__ W_q,
                 const float* __restrict__ W_k, const float* __restrict__ w_b,
                 const float* __restrict__ sW_y, const float* __restrict__ sW_q,
                 const float* __restrict__ sW_k, const float* __restrict__ sw_b,
                 const float* __restrict__ F0) {
    __shared__ __align__(16) float xs[2][DD];
    __shared__ __align__(16) float q_s[2][DD], k_s[2][DD];
    __shared__ __align__(16) float fq_s[2][DD], fk_s[2][DD], fv_s[2][DD];
    __shared__ __align__(16) float beta_s[2][4];
    __shared__ float fb_s[2];

    const int bh   = blockIdx.x;           // b*NH + h
    const int hh   = bh & (NH - 1);
    const int tid  = threadIdx.x;
    const int warp = tid >> 5;
    const int lane = tid & 31;

    // ---- role / column assignment (all warps fully active) ----
    // role 0: Wy col e     role 1: wb col e (warp3 lanes>=1, duplicated)
    // role 2: Wq col e     role 3: Wk col e     role 4: F col e (warp 6)
    int role, e;
    if (warp < 3)            { role = 0; e = warp * 32 + lane; }
    else if (warp == 3) {
        if (lane == 0)       { role = 0; e = 96; }
        else                 { role = 1; e = (lane - 1) & 3; }   // lanes>=5 duplicate
    }
    else if (warp == 4)      { role = 2; e = lane; }
    else if (warp == 5)      { role = 3; e = lane; }
    else                     { role = 4; e = lane; }

    const int bidx = (role == 0) ? 0 : (role == 2) ? 1 : (role == 3) ? 2 : 3;

    // ---- initial column load (state + broadcast weight) ----
    const float* sp;
    const float* wp = nullptr;
    int stride;
    switch (role) {
        case 0: sp = sW_y + (size_t)bh * DD * YD + e; wp = W_y + (size_t)hh * DD * YD + e; stride = YD; break;
        case 1: sp = sw_b + (size_t)bh * DD * 4  + e; wp = w_b + (size_t)hh * DD * 4  + e; stride = 4;  break;
        case 2: sp = sW_q + (size_t)bh * DD * DD + e; wp = W_q + (size_t)hh * DD * DD + e; stride = DD; break;
        case 3: sp = sW_k + (size_t)bh * DD * DD + e; wp = W_k + (size_t)hh * DD * DD + e; stride = DD; break;
        default: sp = F0  + (size_t)bh * DD * DD + e;                                       stride = DD; break;
    }
    u64 c[16];
#pragma unroll
    for (int i = 0; i < 16; i++) {
        float v0 = sp[(2 * i)     * stride];
        float v1 = sp[(2 * i + 1) * stride];
        if (wp) { v0 += wp[(2 * i) * stride]; v1 += wp[(2 * i + 1) * stride]; }
        c[i] = pack2(v0, v1);
    }

    // ---- prologue: warp 6 computes x_0 = softmax(h_0), prefetches h_1 ----
    const float* hrow = h + (size_t)bh * DD + lane;
    float xreg = 0.0f;
    float* gout = g_fwm + (size_t)bh * DD + lane;
    if (role == 4) {
        float p = __expf(hrow[0]);
        float s = wsum(p);
        xs[0][lane] = __fdividef(p, s);
        xreg = hrow[ROWSTRIDE];
    }
    __syncthreads();

    // ---- peeled interval t = 0: matvec only ----
    if (role <= 3) {
        float yv = dot32v(xs[0], c);
        if (warp == 0)       { float p = __expf(yv); float s = wsum(p); fq_s[0][lane] = __fdividef(p, s); }
        else if (warp == 1)  { float p = __expf(yv); float s = wsum(p); fk_s[0][lane] = __fdividef(p, s); }
        else if (warp == 2)  { fv_s[0][lane] = yv; }
        else if (warp == 3)  { float sg = __fdividef(1.0f, 1.0f + __expf(-yv));
                               if (lane == 0) fb_s[0] = sg;
                               else if (lane <= 4) beta_s[0][e] = sg; }
        else if (warp == 4)  { float p = __expf(yv); float s = wsum(p); q_s[0][lane] = __fdividef(p, s); }
        else                 { float p = __expf(yv); float s = wsum(p); k_s[0][lane] = __fdividef(p, s); }
    } else {
        float p = __expf(xreg);
        float s = wsum(p);
        xs[1][lane] = __fdividef(p, s);
        xreg = hrow[(size_t)2 * ROWSTRIDE];
    }
    __syncthreads();

    const u64 neg1 = bcast2(-1.0f);

    // ================= time loop: one barrier per interval =================
    for (int t = 1; t < TT; t++) {
        const int pm = (t - 1) & 1;   // buffers from interval t-1
        const int pc = t & 1;         // buffers produced this interval

        if (role <= 3) {
            const float* qp = q_s[pm];
            const float* kp = k_s[pm];
            const float* xp = xs[pc];
            // scalar chain: s_xk = dot(x_t, k) via lane product + butterfly
            float sxk = wsum(xp[lane] * kp[lane]);
            float bi  = beta_s[pm][bidx];

            // parallel dots on c_old: (q-k)·c and x·c ; keep k for update
            u64 kv[16];
            u64 ad[4] = {0ull, 0ull, 0ull, 0ull};
            u64 ax[4] = {0ull, 0ull, 0ull, 0ull};
#pragma unroll
            for (int i = 0; i < 8; i++) {
                f4u qv = ld4(qp + 4 * i);
                f4u kk = ld4(kp + 4 * i);
                f4u xv = ld4(xp + 4 * i);
                u64 dm0 = ffma2(kk.u[0], neg1, qv.u[0]);   // q - k
                u64 dm1 = ffma2(kk.u[1], neg1, qv.u[1]);
                ad[(2 * i)     & 3] = ffma2(dm0, c[2 * i],     ad[(2 * i)     & 3]);
                ad[(2 * i + 1) & 3] = ffma2(dm1, c[2 * i + 1], ad[(2 * i + 1) & 3]);
                ax[(2 * i)     & 3] = ffma2(xv.u[0], c[2 * i],     ax[(2 * i)     & 3]);
                ax[(2 * i + 1) & 3] = ffma2(xv.u[1], c[2 * i + 1], ax[(2 * i + 1) & 3]);
                kv[2 * i]     = kk.u[0];
                kv[2 * i + 1] = kk.u[1];
            }
            float delta = bi * hsum2(add2(add2(ad[0], ad[1]), add2(ad[2], ad[3])));
            float yv    = hsum2(add2(add2(ax[0], ax[1]), add2(ax[2], ax[3]))) + delta * sxk;

            // activations (critical path) first
            if (warp == 0)       { float p = __expf(yv); float s = wsum(p); fq_s[pc][lane] = __fdividef(p, s); }
            else if (warp == 1)  { float p = __expf(yv); float s = wsum(p); fk_s[pc][lane] = __fdividef(p, s); }
            else if (warp == 2)  { fv_s[pc][lane] = yv; }
            else if (warp == 3)  { float sg = __fdividef(1.0f, 1.0f + __expf(-yv));
                                   if (lane == 0) fb_s[pc] = sg;
                                   else if (lane <= 4) beta_s[pc][e] = sg; }
            else if (warp == 4)  { float p = __expf(yv); float s = wsum(p); q_s[pc][lane] = __fdividef(p, s); }
            else                 { float p = __expf(yv); float s = wsum(p); k_s[pc][lane] = __fdividef(p, s); }

            // off-path state update
            u64 d2 = bcast2(delta);
#pragma unroll
            for (int i = 0; i < 16; i++) c[i] = ffma2(kv[i], d2, c[i]);
        } else {
            // ---- warp 6: FWM step t-1 ----
            {
                const float* fqp = fq_s[pm];
                const float* fkp = fk_s[pm];
                float sqk = wsum(fqp[lane] * fkp[lane]);
                float fb  = fb_s[pm];
                float fvd = fv_s[pm][lane];

                u64 kv[16];
                u64 av[4] = {0ull, 0ull, 0ull, 0ull};
                u64 ao[4] = {0ull, 0ull, 0ull, 0ull};
#pragma unroll
                for (int i = 0; i < 8; i++) {
                    f4u fqv = ld4(fqp + 4 * i);
                    f4u fkv = ld4(fkp + 4 * i);
                    av[(2 * i)     & 3] = ffma2(fkv.u[0], c[2 * i],     av[(2 * i)     & 3]);
                    av[(2 * i + 1) & 3] = ffma2(fkv.u[1], c[2 * i + 1], av[(2 * i + 1) & 3]);
                    ao[(2 * i)     & 3] = ffma2(fqv.u[0], c[2 * i],     ao[(2 * i)     & 3]);
                    ao[(2 * i + 1) & 3] = ffma2(fqv.u[1], c[2 * i + 1], ao[(2 * i + 1) & 3]);
                    kv[2 * i]     = fkv.u[0];
                    kv[2 * i + 1] = fkv.u[1];
                }
                float vold = hsum2(add2(add2(av[0], av[1]), add2(av[2], av[3])));
                float outq = hsum2(add2(add2(ao[0], ao[1]), add2(ao[2], ao[3])));
                float delta = fb * (fvd - vold);
                gout[(size_t)(t - 1) * ROWSTRIDE] = outq + delta * sqk;
                u64 d2 = bcast2(delta);
#pragma unroll
                for (int i = 0; i < 16; i++) c[i] = ffma2(kv[i], d2, c[i]);
            }
            // ---- stage x_{t+1}, prefetch h_{t+2} ----
            {
                float p = __expf(xreg);
                float s = wsum(p);
                xs[(t + 1) & 1][lane] = __fdividef(p, s);
                xreg = (t + 2 < TT) ? hrow[(size_t)(t + 2) * ROWSTRIDE] : 0.0f;
            }
        }
        __syncthreads();
    }

    // ---- epilogue: FWM step TT-1 ----
    if (role == 4) {
        const int pm = (TT - 1) & 1;
        const float* fqp = fq_s[pm];
        const float* fkp = fk_s[pm];
        float sqk = wsum(fqp[lane] * fkp[lane]);
        u64 av[4] = {0ull, 0ull, 0ull, 0ull};
        u64 ao[4] = {0ull, 0ull, 0ull, 0ull};
#pragma unroll
        for (int i = 0; i < 8; i++) {
            f4u fqv = ld4(fqp + 4 * i);
            f4u fkv = ld4(fkp + 4 * i);
            av[(2 * i)     & 3] = ffma2(fkv.u[0], c[2 * i],     av[(2 * i)     & 3]);
            av[(2 * i + 1) & 3] = ffma2(fkv.u[1], c[2 * i + 1], av[(2 * i + 1) & 3]);
            ao[(2 * i)     & 3] = ffma2(fqv.u[0], c[2 * i],     ao[(2 * i)     & 3]);
            ao[(2 * i + 1) & 3] = ffma2(fqv.u[1], c[2 * i + 1], ao[(2 * i + 1) & 3]);
        }
        float vold = hsum2(add2(add2(av[0], av[1]), add2(av[2], av[3])));
        float outq = hsum2(add2(add2(ao[0], ao[1]), add2(ao[2], ao[3])));
        float delta = fb_s[pm] * (fv_s[pm][lane] - vold);
        gout[(size_t)(TT - 1) * ROWSTRIDE] = outq + delta * sqk;
    }
}

// ======================================================================
// Kernel 2: out = h + g_fwm @ W_out^T    (M=32768, N=256, K=256)
// BM=128, BN=64, BK=32, 256 threads, 8x4 f32x2 thread tile,
// 2-stage double-buffered smem, one __syncthreads per k-tile.
// ======================================================================
#define GBM 128
#define GBN 64
#define GBK 32
#define ALDA (GBM + 4)
#define BLDA (GBN + 4)

__global__ __launch_bounds__(256)
void out_gemm_kernel(const float* __restrict__ W,   // W_out [n][k], 256x256
                     const float* __restrict__ h,
                     float* __restrict__ out) {
    __shared__ __align__(16) float As[2][GBK][ALDA];
    __shared__ __align__(16) float Bs[2][GBK][BLDA];

    const int tid = threadIdx.x;
    const int m0  = blockIdx.x * GBM;
    const int n0  = blockIdx.y * GBN;
    const int ty  = tid >> 4;
    const int tx  = tid & 15;

    const int a_row = tid >> 3;
    const int a_kv  = (tid & 7) * 4;
    const int b_row = tid >> 3;
    const int b_kv  = (tid & 7) * 4;

    u64 acc[8][2];
#pragma unroll
    for (int i = 0; i < 8; i++) { acc[i][0] = 0ull; acc[i][1] = 0ull; }

    const int NT = INDIM / GBK;

    float4 ar[4], br[2];
#pragma unroll
    for (int r = 0; r < 4; r++)
        ar[r] = *(const float4*)(g_fwm + (size_t)(m0 + a_row + r * 32) * INDIM + a_kv);
#pragma unroll
    for (int r = 0; r < 2; r++)
        br[r] = *(const float4*)(W + (size_t)(n0 + b_row + r * 32) * INDIM + b_kv);
#pragma unroll
    for (int r = 0; r < 4; r++) {
        int row = a_row + r * 32;
        As[0][a_kv + 0][row] = ar[r].x; As[0][a_kv + 1][row] = ar[r].y;
        As[0][a_kv + 2][row] = ar[r].z; As[0][a_kv + 3][row] = ar[r].w;
    }
#pragma unroll
    for (int r = 0; r < 2; r++) {
        int row = b_row + r * 32;
        Bs[0][b_kv + 0][row] = br[r].x; Bs[0][b_kv + 1][row] = br[r].y;
        Bs[0][b_kv + 2][row] = br[r].z; Bs[0][b_kv + 3][row] = br[r].w;
    }
    __syncthreads();

    for (int kt = 0; kt < NT; kt++) {
        const int s = kt & 1;
        if (kt + 1 < NT) {
            const int ko = (kt + 1) * GBK;
#pragma unroll
            for (int r = 0; r < 4; r++)
                ar[r] = *(const float4*)(g_fwm + (size_t)(m0 + a_row + r * 32) * INDIM + ko + a_kv);
#pragma unroll
            for (int r = 0; r < 2; r++)
                br[r] = *(const float4*)(W + (size_t)(n0 + b_row + r * 32) * INDIM + ko + b_kv);
        }
#pragma unroll
        for (int k = 0; k < GBK; k++) {
            f4u a0 = ld4(&As[s][k][ty * 8]);
            f4u a1 = ld4(&As[s][k][ty * 8 + 4]);
            f4u b  = ld4(&Bs[s][k][tx * 4]);
            u64 p;
            float av[8];
            av[0] = a0.f.x; av[1] = a0.f.y; av[2] = a0.f.z; av[3] = a0.f.w;
            av[4] = a1.f.x; av[5] = a1.f.y; av[6] = a1.f.z; av[7] = a1.f.w;
#pragma unroll
            for (int i = 0; i < 8; i++) {
                p = bcast2(av[i]);
                acc[i][0] = ffma2(p, b.u[0], acc[i][0]);
                acc[i][1] = ffma2(p, b.u[1], acc[i][1]);
            }
        }
        if (kt + 1 < NT) {
            const int d = s ^ 1;
#pragma unroll
            for (int r = 0; r < 4; r++) {
                int row = a_row + r * 32;
                As[d][a_kv + 0][row] = ar[r].x; As[d][a_kv + 1][row] = ar[r].y;
                As[d][a_kv + 2][row] = ar[r].z; As[d][a_kv + 3][row] = ar[r].w;
            }
#pragma unroll
            for (int r = 0; r < 2; r++) {
                int row = b_row + r * 32;
                Bs[d][b_kv + 0][row] = br[r].x; Bs[d][b_kv + 1][row] = br[r].y;
                Bs[d][b_kv + 2][row] = br[r].z; Bs[d][b_kv + 3][row] = br[r].w;
            }
            __syncthreads();
        }
    }

#pragma unroll
    for (int i = 0; i < 8; i++) {
        int row = m0 + ty * 8 + i;
        const float* hp = h + (size_t)row * INDIM + n0 + tx * 4;
        float4 hv = *(const float4*)hp;
        float a, b, cc, d;
        asm("mov.b64 {%0, %1}, %2;" : "=f"(a), "=f"(b) : "l"(acc[i][0]));
        asm("mov.b64 {%0, %1}, %2;" : "=f"(cc), "=f"(d) : "l"(acc[i][1]));
        float4 o;
        o.x = hv.x + a; o.y = hv.y + b; o.z = hv.z + cc; o.w = hv.w + d;
        *(float4*)(out + (size_t)row * INDIM + n0 + tx * 4) = o;
    }
}

// ======================================================================
extern "C" void kernel_launch(void* const* d_in, const int* in_sizes, int n_in,
                              void* d_out, int out_size) {
    const float* h     = (const float*)d_in[0];
    const float* W_y   = (const float*)d_in[1];
    const float* W_q   = (const float*)d_in[2];
    const float* W_k   = (const float*)d_in[3];
    const float* w_b   = (const float*)d_in[4];
    const float* W_out = (const float*)d_in[5];
    const float* sW_y  = (const float*)d_in[6];
    const float* sW_q  = (const float*)d_in[7];
    const float* sW_k  = (const float*)d_in[8];
    const float* sw_b  = (const float*)d_in[9];
    const float* F0    = (const float*)d_in[10];
    float* out = (float*)d_out;

    srwm_kernel<<<BB * NH, 224>>>(h, W_y, W_q, W_k, w_b, sW_y, sW_q, sW_k, sw_b, F0);

    dim3 ggrid((TT * BB) / GBM, INDIM / GBN);
    out_gemm_kernel<<<ggrid, 256>>>(W_out, h, out);
}

// round 9
// speedup vs baseline: 1.9153x; 1.0084x over previous
#include <cuda_runtime.h>
#include <cuda_bf16.h>
#include <cstdint>

// Problem constants
#define TT   1024
#define BB   32
#define NH   8
#define DD   32
#define YD   97
#define INDIM 256          // NH*DD
#define ROWSTRIDE 8192     // BB*INDIM

typedef unsigned long long u64;

// -------- scratch (device globals; no allocation allowed) ----------
__device__ float g_fwm[(size_t)TT * BB * INDIM];   // FWM output pre-GEMM, 33.5 MB

// -------- packed f32x2 helpers ----------
__device__ __forceinline__ u64 ffma2(u64 a, u64 b, u64 c) {
    u64 d;
    asm("fma.rn.f32x2 %0, %1, %2, %3;" : "=l"(d) : "l"(a), "l"(b), "l"(c));
    return d;
}
__device__ __forceinline__ u64 add2(u64 a, u64 b) {
    u64 d;
    asm("add.rn.f32x2 %0, %1, %2;" : "=l"(d) : "l"(a), "l"(b));
    return d;
}
__device__ __forceinline__ u64 pack2(float a, float b) {
    u64 r;
    asm("mov.b64 %0, {%1, %2};" : "=l"(r) : "f"(a), "f"(b));
    return r;
}
__device__ __forceinline__ u64 bcast2(float a) {
    u64 r;
    asm("mov.b64 %0, {%1, %1};" : "=l"(r) : "f"(a));
    return r;
}
__device__ __forceinline__ float hsum2(u64 v) {
    float a, b;
    asm("mov.b64 {%0, %1}, %2;" : "=f"(a), "=f"(b) : "l"(v));
    return a + b;
}

// float4 viewed as two packed f32x2
union f4u {
    float4 f;
    u64    u[2];
};
__device__ __forceinline__ f4u ld4(const float* p) {
    f4u r;
    r.f = *(const float4*)p;   // LDS.128
    return r;
}

// -------- warp sum (5-round SHFL butterfly; f32 REDUX absent on sm_103) ----
__device__ __forceinline__ float wsum(float v) {
#pragma unroll
    for (int o = 16; o; o >>= 1) v += __shfl_xor_sync(0xffffffffu, v, o);
    return v;
}

// -------- dot(x[0:32], column) via 8 LDS.128 + 16 FFMA2 (peel only) --------
__device__ __forceinline__ float dot32v(const float* __restrict__ xp, const u64* c) {
    u64 a0 = 0ull, a1 = 0ull, a2 = 0ull, a3 = 0ull;
#pragma unroll
    for (int i = 0; i < 4; i++) {
        f4u x0 = ld4(xp + 8 * i);
        f4u x1 = ld4(xp + 8 * i + 4);
        a0 = ffma2(x0.u[0], c[4 * i],     a0);
        a1 = ffma2(x0.u[1], c[4 * i + 1], a1);
        a2 = ffma2(x1.u[0], c[4 * i + 2], a2);
        a3 = ffma2(x1.u[1], c[4 * i + 3], a3);
    }
    return hsum2(add2(add2(a0, a1), add2(a2, a3)));
}

// ======================================================================
// Kernel 1: fused softmax(h) + SRWM + FWM recurrence. One CTA per (b,h).
// 8 warps: roles 0-3 = SRWM column warps, role 4 (warp 6) = FWM only,
// role 5 (warp 7) = dedicated x-softmax staging (off the FWM chain).
// One barrier per step (double-buffered broadcast vectors).
// ======================================================================
__global__ __launch_bounds__(256, 2)
void srwm_kernel(const float* __restrict__ h,
                 const float* __restrict__ W_y, const float* __restrict__ W_q,
                 const float* __restrict__ W_k, const float* __restrict__ w_b,
                 const float* __restrict__ sW_y, const float* __restrict__ sW_q,
                 const float* __restrict__ sW_k, const float* __restrict__ sw_b,
                 const float* __restrict__ F0) {
    __shared__ __align__(16) float xs[2][DD];
    __shared__ __align__(16) float q_s[2][DD], k_s[2][DD];
    __shared__ __align__(16) float fq_s[2][DD], fk_s[2][DD], fv_s[2][DD];
    __shared__ __align__(16) float beta_s[2][4];
    __shared__ float fb_s[2];

    const int bh   = blockIdx.x;           // b*NH + h
    const int hh   = bh & (NH - 1);
    const int tid  = threadIdx.x;
    const int warp = tid >> 5;
    const int lane = tid & 31;

    // ---- role / column assignment ----
    // role 0: Wy col e   role 1: wb col e (warp3 lanes>=1, duplicated)
    // role 2: Wq col e   role 3: Wk col e
    // role 4: F col e (warp 6, FWM only)   role 5: x staging (warp 7)
    int role, e;
    if (warp < 3)            { role = 0; e = warp * 32 + lane; }
    else if (warp == 3) {
        if (lane == 0)       { role = 0; e = 96; }
        else                 { role = 1; e = (lane - 1) & 3; }   // lanes>=5 duplicate
    }
    else if (warp == 4)      { role = 2; e = lane; }
    else if (warp == 5)      { role = 3; e = lane; }
    else if (warp == 6)      { role = 4; e = lane; }
    else                     { role = 5; e = lane; }

    const int bidx = (role == 0) ? 0 : (role == 2) ? 1 : (role == 3) ? 2 : 3;

    // ---- initial column load (state + broadcast weight) ----
    u64 c[16];
#pragma unroll
    for (int i = 0; i < 16; i++) c[i] = 0ull;
    if (role <= 4) {
        const float* sp;
        const float* wp = nullptr;
        int stride;
        switch (role) {
            case 0: sp = sW_y + (size_t)bh * DD * YD + e; wp = W_y + (size_t)hh * DD * YD + e; stride = YD; break;
            case 1: sp = sw_b + (size_t)bh * DD * 4  + e; wp = w_b + (size_t)hh * DD * 4  + e; stride = 4;  break;
            case 2: sp = sW_q + (size_t)bh * DD * DD + e; wp = W_q + (size_t)hh * DD * DD + e; stride = DD; break;
            case 3: sp = sW_k + (size_t)bh * DD * DD + e; wp = W_k + (size_t)hh * DD * DD + e; stride = DD; break;
            default: sp = F0  + (size_t)bh * DD * DD + e;                                       stride = DD; break;
        }
#pragma unroll
        for (int i = 0; i < 16; i++) {
            float v0 = sp[(2 * i)     * stride];
            float v1 = sp[(2 * i + 1) * stride];
            if (wp) { v0 += wp[(2 * i) * stride]; v1 += wp[(2 * i + 1) * stride]; }
            c[i] = pack2(v0, v1);
        }
    }

    // ---- prologue: warp 7 computes x_0 = softmax(h_0), prefetches h_1 ----
    const float* hrow = h + (size_t)bh * DD + lane;
    float xreg = 0.0f;
    float* gout = g_fwm + (size_t)bh * DD + lane;
    if (role == 5) {
        float p = __expf(hrow[0]);
        float s = wsum(p);
        xs[0][lane] = __fdividef(p, s);
        xreg = hrow[ROWSTRIDE];
    }
    __syncthreads();

    // ---- peeled interval t = 0: matvec only ----
    if (role <= 3) {
        float yv = dot32v(xs[0], c);
        if (warp == 0)       { float p = __expf(yv); float s = wsum(p); fq_s[0][lane] = __fdividef(p, s); }
        else if (warp == 1)  { float p = __expf(yv); float s = wsum(p); fk_s[0][lane] = __fdividef(p, s); }
        else if (warp == 2)  { fv_s[0][lane] = yv; }
        else if (warp == 3)  { float sg = __fdividef(1.0f, 1.0f + __expf(-yv));
                               if (lane == 0) fb_s[0] = sg;
                               else if (lane <= 4) beta_s[0][e] = sg; }
        else if (warp == 4)  { float p = __expf(yv); float s = wsum(p); q_s[0][lane] = __fdividef(p, s); }
        else                 { float p = __expf(yv); float s = wsum(p); k_s[0][lane] = __fdividef(p, s); }
    } else if (role == 5) {
        float p = __expf(xreg);
        float s = wsum(p);
        xs[1][lane] = __fdividef(p, s);
        xreg = hrow[(size_t)2 * ROWSTRIDE];
    }
    __syncthreads();

    const u64 neg1 = bcast2(-1.0f);

    // ================= time loop: one barrier per interval =================
    for (int t = 1; t < TT; t++) {
        const int pm = (t - 1) & 1;   // buffers from interval t-1
        const int pc = t & 1;         // buffers produced this interval

        if (role <= 3) {
            const float* qp = q_s[pm];
            const float* kp = k_s[pm];
            const float* xp = xs[pc];
            // scalar chain: s_xk = dot(x_t, k) via lane product + butterfly
            float sxk = wsum(xp[lane] * kp[lane]);
            float bi  = beta_s[pm][bidx];

            // parallel dots on c_old: (q-k)·c and x·c ; keep k for update
            u64 kv[16];
            u64 ad[4] = {0ull, 0ull, 0ull, 0ull};
            u64 ax[4] = {0ull, 0ull, 0ull, 0ull};
#pragma unroll
            for (int i = 0; i < 8; i++) {
                f4u qv = ld4(qp + 4 * i);
                f4u kk = ld4(kp + 4 * i);
                f4u xv = ld4(xp + 4 * i);
                u64 dm0 = ffma2(kk.u[0], neg1, qv.u[0]);   // q - k
                u64 dm1 = ffma2(kk.u[1], neg1, qv.u[1]);
                ad[(2 * i)     & 3] = ffma2(dm0, c[2 * i],     ad[(2 * i)     & 3]);
                ad[(2 * i + 1) & 3] = ffma2(dm1, c[2 * i + 1], ad[(2 * i + 1) & 3]);
                ax[(2 * i)     & 3] = ffma2(xv.u[0], c[2 * i],     ax[(2 * i)     & 3]);
                ax[(2 * i + 1) & 3] = ffma2(xv.u[1], c[2 * i + 1], ax[(2 * i + 1) & 3]);
                kv[2 * i]     = kk.u[0];
                kv[2 * i + 1] = kk.u[1];
            }
            float delta = bi * hsum2(add2(add2(ad[0], ad[1]), add2(ad[2], ad[3])));
            float yv    = hsum2(add2(add2(ax[0], ax[1]), add2(ax[2], ax[3]))) + delta * sxk;

            // activations (critical path) first
            if (warp == 0)       { float p = __expf(yv); float s = wsum(p); fq_s[pc][lane] = __fdividef(p, s); }
            else if (warp == 1)  { float p = __expf(yv); float s = wsum(p); fk_s[pc][lane] = __fdividef(p, s); }
            else if (warp == 2)  { fv_s[pc][lane] = yv; }
            else if (warp == 3)  { float sg = __fdividef(1.0f, 1.0f + __expf(-yv));
                                   if (lane == 0) fb_s[pc] = sg;
                                   else if (lane <= 4) beta_s[pc][e] = sg; }
            else if (warp == 4)  { float p = __expf(yv); float s = wsum(p); q_s[pc][lane] = __fdividef(p, s); }
            else                 { float p = __expf(yv); float s = wsum(p); k_s[pc][lane] = __fdividef(p, s); }

            // off-path state update
            u64 d2 = bcast2(delta);
#pragma unroll
            for (int i = 0; i < 16; i++) c[i] = ffma2(kv[i], d2, c[i]);
        } else if (role == 4) {
            // ---- warp 6: FWM step t-1 (only task) ----
            const float* fqp = fq_s[pm];
            const float* fkp = fk_s[pm];
            float sqk = wsum(fqp[lane] * fkp[lane]);
            float fb  = fb_s[pm];
            float fvd = fv_s[pm][lane];

            u64 kv[16];
            u64 av[4] = {0ull, 0ull, 0ull, 0ull};
            u64 ao[4] = {0ull, 0ull, 0ull, 0ull};
#pragma unroll
            for (int i = 0; i < 8; i++) {
                f4u fqv = ld4(fqp + 4 * i);
                f4u fkv = ld4(fkp + 4 * i);
                av[(2 * i)     & 3] = ffma2(fkv.u[0], c[2 * i],     av[(2 * i)     & 3]);
                av[(2 * i + 1) & 3] = ffma2(fkv.u[1], c[2 * i + 1], av[(2 * i + 1) & 3]);
                ao[(2 * i)     & 3] = ffma2(fqv.u[0], c[2 * i],     ao[(2 * i)     & 3]);
                ao[(2 * i + 1) & 3] = ffma2(fqv.u[1], c[2 * i + 1], ao[(2 * i + 1) & 3]);
                kv[2 * i]     = fkv.u[0];
                kv[2 * i + 1] = fkv.u[1];
            }
            float vold = hsum2(add2(add2(av[0], av[1]), add2(av[2], av[3])));
            float outq = hsum2(add2(add2(ao[0], ao[1]), add2(ao[2], ao[3])));
            float delta = fb * (fvd - vold);
            gout[(size_t)(t - 1) * ROWSTRIDE] = outq + delta * sqk;
            u64 d2 = bcast2(delta);
#pragma unroll
            for (int i = 0; i < 16; i++) c[i] = ffma2(kv[i], d2, c[i]);
        } else {
            // ---- warp 7: stage x_{t+1}, prefetch h_{t+2} ----
            float p = __expf(xreg);
            float s = wsum(p);
            xs[(t + 1) & 1][lane] = __fdividef(p, s);
            xreg = (t + 2 < TT) ? hrow[(size_t)(t + 2) * ROWSTRIDE] : 0.0f;
        }
        __syncthreads();
    }

    // ---- epilogue: FWM step TT-1 ----
    if (role == 4) {
        const int pm = (TT - 1) & 1;
        const float* fqp = fq_s[pm];
        const float* fkp = fk_s[pm];
        float sqk = wsum(fqp[lane] * fkp[lane]);
        u64 av[4] = {0ull, 0ull, 0ull, 0ull};
        u64 ao[4] = {0ull, 0ull, 0ull, 0ull};
#pragma unroll
        for (int i = 0; i < 8; i++) {
            f4u fqv = ld4(fqp + 4 * i);
            f4u fkv = ld4(fkp + 4 * i);
            av[(2 * i)     & 3] = ffma2(fkv.u[0], c[2 * i],     av[(2 * i)     & 3]);
            av[(2 * i + 1) & 3] = ffma2(fkv.u[1], c[2 * i + 1], av[(2 * i + 1) & 3]);
            ao[(2 * i)     & 3] = ffma2(fqv.u[0], c[2 * i],     ao[(2 * i)     & 3]);
            ao[(2 * i + 1) & 3] = ffma2(fqv.u[1], c[2 * i + 1], ao[(2 * i + 1) & 3]);
        }
        float vold = hsum2(add2(add2(av[0], av[1]), add2(av[2], av[3])));
        float outq = hsum2(add2(add2(ao[0], ao[1]), add2(ao[2], ao[3])));
        float delta = fb_s[pm] * (fv_s[pm][lane] - vold);
        gout[(size_t)(TT - 1) * ROWSTRIDE] = outq + delta * sqk;
    }
}

// ======================================================================
// Kernel 2: out = h + g_fwm @ W_out^T    (M=32768, N=256, K=256)
// BM=128, BN=64, BK=32, 256 threads, 8x4 f32x2 thread tile,
// 2-stage double-buffered smem, one __syncthreads per k-tile.
// ======================================================================
#define GBM 128
#define GBN 64
#define GBK 32
#define ALDA (GBM + 4)
#define BLDA (GBN + 4)

__global__ __launch_bounds__(256)
void out_gemm_kernel(const float* __restrict__ W,   // W_out [n][k], 256x256
                     const float* __restrict__ h,
                     float* __restrict__ out) {
    __shared__ __align__(16) float As[2][GBK][ALDA];
    __shared__ __align__(16) float Bs[2][GBK][BLDA];

    const int tid = threadIdx.x;
    const int m0  = blockIdx.x * GBM;
    const int n0  = blockIdx.y * GBN;
    const int ty  = tid >> 4;
    const int tx  = tid & 15;

    const int a_row = tid >> 3;
    const int a_kv  = (tid & 7) * 4;
    const int b_row = tid >> 3;
    const int b_kv  = (tid & 7) * 4;

    u64 acc[8][2];
#pragma unroll
    for (int i = 0; i < 8; i++) { acc[i][0] = 0ull; acc[i][1] = 0ull; }

    const int NT = INDIM / GBK;

    float4 ar[4], br[2];
#pragma unroll
    for (int r = 0; r < 4; r++)
        ar[r] = *(const float4*)(g_fwm + (size_t)(m0 + a_row + r * 32) * INDIM + a_kv);
#pragma unroll
    for (int r = 0; r < 2; r++)
        br[r] = *(const float4*)(W + (size_t)(n0 + b_row + r * 32) * INDIM + b_kv);
#pragma unroll
    for (int r = 0; r < 4; r++) {
        int row = a_row + r * 32;
        As[0][a_kv + 0][row] = ar[r].x; As[0][a_kv + 1][row] = ar[r].y;
        As[0][a_kv + 2][row] = ar[r].z; As[0][a_kv + 3][row] = ar[r].w;
    }
#pragma unroll
    for (int r = 0; r < 2; r++) {
        int row = b_row + r * 32;
        Bs[0][b_kv + 0][row] = br[r].x; Bs[0][b_kv + 1][row] = br[r].y;
        Bs[0][b_kv + 2][row] = br[r].z; Bs[0][b_kv + 3][row] = br[r].w;
    }
    __syncthreads();

    for (int kt = 0; kt < NT; kt++) {
        const int s = kt & 1;
        if (kt + 1 < NT) {
            const int ko = (kt + 1) * GBK;
#pragma unroll
            for (int r = 0; r < 4; r++)
                ar[r] = *(const float4*)(g_fwm + (size_t)(m0 + a_row + r * 32) * INDIM + ko + a_kv);
#pragma unroll
            for (int r = 0; r < 2; r++)
                br[r] = *(const float4*)(W + (size_t)(n0 + b_row + r * 32) * INDIM + ko + b_kv);
        }
#pragma unroll
        for (int k = 0; k < GBK; k++) {
            f4u a0 = ld4(&As[s][k][ty * 8]);
            f4u a1 = ld4(&As[s][k][ty * 8 + 4]);
            f4u b  = ld4(&Bs[s][k][tx * 4]);
            u64 p;
            float av[8];
            av[0] = a0.f.x; av[1] = a0.f.y; av[2] = a0.f.z; av[3] = a0.f.w;
            av[4] = a1.f.x; av[5] = a1.f.y; av[6] = a1.f.z; av[7] = a1.f.w;
#pragma unroll
            for (int i = 0; i < 8; i++) {
                p = bcast2(av[i]);
                acc[i][0] = ffma2(p, b.u[0], acc[i][0]);
                acc[i][1] = ffma2(p, b.u[1], acc[i][1]);
            }
        }
        if (kt + 1 < NT) {
            const int d = s ^ 1;
#pragma unroll
            for (int r = 0; r < 4; r++) {
                int row = a_row + r * 32;
                As[d][a_kv + 0][row] = ar[r].x; As[d][a_kv + 1][row] = ar[r].y;
                As[d][a_kv + 2][row] = ar[r].z; As[d][a_kv + 3][row] = ar[r].w;
            }
#pragma unroll
            for (int r = 0; r < 2; r++) {
                int row = b_row + r * 32;
                Bs[d][b_kv + 0][row] = br[r].x; Bs[d][b_kv + 1][row] = br[r].y;
                Bs[d][b_kv + 2][row] = br[r].z; Bs[d][b_kv + 3][row] = br[r].w;
            }
            __syncthreads();
        }
    }

#pragma unroll
    for (int i = 0; i < 8; i++) {
        int row = m0 + ty * 8 + i;
        const float* hp = h + (size_t)row * INDIM + n0 + tx * 4;
        float4 hv = *(const float4*)hp;
        float a, b, cc, d;
        asm("mov.b64 {%0, %1}, %2;" : "=f"(a), "=f"(b) : "l"(acc[i][0]));
        asm("mov.b64 {%0, %1}, %2;" : "=f"(cc), "=f"(d) : "l"(acc[i][1]));
        float4 o;
        o.x = hv.x + a; o.y = hv.y + b; o.z = hv.z + cc; o.w = hv.w + d;
        *(float4*)(out + (size_t)row * INDIM + n0 + tx * 4) = o;
    }
}

// ======================================================================
extern "C" void kernel_launch(void* const* d_in, const int* in_sizes, int n_in,
                              void* d_out, int out_size) {
    const float* h     = (const float*)d_in[0];
    const float* W_y   = (const float*)d_in[1];
    const float* W_q   = (const float*)d_in[2];
    const float* W_k   = (const float*)d_in[3];
    const float* w_b   = (const float*)d_in[4];
    const float* W_out = (const float*)d_in[5];
    const float* sW_y  = (const float*)d_in[6];
    const float* sW_q  = (const float*)d_in[7];
    const float* sW_k  = (const float*)d_in[8];
    const float* sw_b  = (const float*)d_in[9];
    const float* F0    = (const float*)d_in[10];
    float* out = (float*)d_out;

    srwm_kernel<<<BB * NH, 256>>>(h, W_y, W_q, W_k, w_b, sW_y, sW_q, sW_k, sw_b, F0);

    dim3 ggrid((TT * BB) / GBM, INDIM / GBN);
    out_gemm_kernel<<<ggrid, 256>>>(W_out, h, out);
}